// round 6
// baseline (speedup 1.0000x reference)
#include <cuda_runtime.h>
#include <math.h>

// Fixed-shape problem: N=16384, D=8, pid in [0,2000), K=128, R=1
#define NMAX    16384
#define NPIDMAX 2048
#define KSEL2   129     // top-(K+1) including self (self weight = 0)
#define CPT     8       // condensation points per repulsion block
#define RT      256     // threads per block
#define NB      256     // histogram bins over d2 in [0,1]
#define BCAP    128     // boundary-bin candidate capacity per CP

// -------- device scratch (small, allocation-free) --------
__device__ unsigned long long g_best[NPIDMAX];   // per-pid packed (beta_bits<<32 | ~idx)
__device__ float  g_q[NMAX];
__device__ float4 g_pack[NMAX * 3];              // per-j: {x0..3},{x4..7},{n2,q,pid,0}
__device__ int    g_cplist[NPIDMAX];
__device__ int    g_cpcount;
__device__ double g_att;
__device__ double g_rep;
__device__ int    g_maskcnt;

__global__ void k_init() {
    int i = blockIdx.x * blockDim.x + threadIdx.x;
    if (i < NPIDMAX) g_best[i] = 0ULL;
    if (i == 0) { g_cpcount = 0; g_att = 0.0; g_rep = 0.0; g_maskcnt = 0; }
}

// q = arctanh(beta)^2 + 0.01 ; pack {x, n2, q, pid} ; per-pid best
__global__ void k_bestq(const float* __restrict__ beta, const int* __restrict__ pid,
                        const float* __restrict__ x, int N) {
    int i = blockIdx.x * blockDim.x + threadIdx.x;
    if (i >= N) return;
    float b = beta[i];
    float t = atanhf(b);
    float q = t * t + 0.01f;
    g_q[i] = q;
    float4 v0 = *(const float4*)(x + (size_t)i * 8);
    float4 v1 = *(const float4*)(x + (size_t)i * 8 + 4);
    float n2 = v0.x * v0.x + v0.y * v0.y + v0.z * v0.z + v0.w * v0.w
             + v1.x * v1.x + v1.y * v1.y + v1.z * v1.z + v1.w * v1.w;
    int p = pid[i];
    g_pack[3 * i + 0] = v0;
    g_pack[3 * i + 1] = v1;
    g_pack[3 * i + 2] = make_float4(n2, q, __int_as_float(p), 0.0f);
    if (p > 0 && p < NPIDMAX) {
        unsigned long long key =
            ((unsigned long long)__float_as_uint(b) << 32) |
            (unsigned long long)(0xFFFFFFFFu - (unsigned)i);
        atomicMax(&g_best[p], key);
    }
}

// compact (threads < NPIDMAX) + attraction, fused
__global__ void k_attract(const float* __restrict__ x, const int* __restrict__ pid,
                          const int* __restrict__ recon, const float* __restrict__ pt,
                          const float* __restrict__ eta, int N) {
    int i = blockIdx.x * blockDim.x + threadIdx.x;
    if (i > 0 && i < NPIDMAX) {
        unsigned long long key = g_best[i];
        if (key != 0ULL) {
            int idx = (int)(0xFFFFFFFFu - (unsigned)(key & 0xFFFFFFFFull));
            int pos = atomicAdd(&g_cpcount, 1);
            g_cplist[pos] = idx;
        }
    }
    float va = 0.0f; int m = 0;
    if (i < N) {
        int p = pid[i];
        if (p > 0 && pt[i] > 0.9f && recon[i] > 0 && fabsf(eta[i]) < 4.0f) {
            unsigned long long key = g_best[p];
            int a = (int)(0xFFFFFFFFu - (unsigned)(key & 0xFFFFFFFFull));
            const float4* xi = (const float4*)(x + (size_t)i * 8);
            const float4* xa = (const float4*)(x + (size_t)a * 8);
            float4 i0 = xi[0], i1 = xi[1], a0 = xa[0], a1 = xa[1];
            float d, d2 = 0.0f;
            d = i0.x - a0.x; d2 += d * d;
            d = i0.y - a0.y; d2 += d * d;
            d = i0.z - a0.z; d2 += d * d;
            d = i0.w - a0.w; d2 += d * d;
            d = i1.x - a1.x; d2 += d * d;
            d = i1.y - a1.y; d2 += d * d;
            d = i1.z - a1.z; d2 += d * d;
            d = i1.w - a1.w; d2 += d * d;
            va = d2 * g_q[i] * g_q[a];
            m = 1;
        }
    }
    #pragma unroll
    for (int o = 16; o; o >>= 1) {
        va += __shfl_down_sync(0xFFFFFFFFu, va, o);
        m  += __shfl_down_sync(0xFFFFFFFFu, m,  o);
    }
    if ((threadIdx.x & 31) == 0 && (m || va != 0.0f)) {
        atomicAdd(&g_att, (double)va);
        atomicAdd(&g_maskcnt, m);
    }
}

// ---- repulsion: pass A = count+weight histograms; pass B = boundary gather only ----
__global__ void __launch_bounds__(RT, 2) k_repulse(int N) {
    __shared__ int      s_hist[CPT][NB];
    __shared__ float    s_whist[CPT][NB];
    __shared__ int      s_Bs[CPT];
    __shared__ int      s_rs[CPT];
    __shared__ float    s_wsum[CPT];
    __shared__ int      s_bcnt[CPT];
    __shared__ unsigned s_bk[CPT][BCAP];
    __shared__ float    s_bw[CPT][BCAP];
    __shared__ int      s_pidc[CPT];
    __shared__ float    s_qc[CPT];
    __shared__ float    s_red[RT / 32];

    int tid   = threadIdx.x;
    int ncp   = g_cpcount;
    int cbase = blockIdx.x * CPT;
    if (cbase >= ncp) return;

    // register-resident CP coords/norms (padded slots never hit radius)
    float xc[CPT][8], n2c[CPT];
    #pragma unroll
    for (int c = 0; c < CPT; c++) {
        int slot = cbase + c;
        bool act = slot < ncp;
        int ci = act ? g_cplist[slot] : 0;
        float4 p0 = g_pack[3 * ci + 0];
        float4 p1 = g_pack[3 * ci + 1];
        float4 p2 = g_pack[3 * ci + 2];
        xc[c][0] = p0.x; xc[c][1] = p0.y; xc[c][2] = p0.z; xc[c][3] = p0.w;
        xc[c][4] = p1.x; xc[c][5] = p1.y; xc[c][6] = p1.z; xc[c][7] = p1.w;
        n2c[c] = act ? p2.x : 1e30f;
        if (tid == 0) { s_pidc[c] = act ? __float_as_int(p2.z) : -1; s_qc[c] = act ? p2.y : 0.0f; }
    }

    for (int h = tid; h < CPT * NB; h += RT) { ((int*)s_hist)[h] = 0; ((float*)s_whist)[h] = 0.0f; }
    if (tid < CPT) s_bcnt[tid] = 0;
    __syncthreads();

    // ---- Pass A: count + weight histograms ----
    for (int j = tid; j < N; j += RT) {
        float4 v0 = g_pack[3 * j + 0];
        float4 v1 = g_pack[3 * j + 1];
        float4 v2 = g_pack[3 * j + 2];
        float n2j = v2.x, qj = v2.y;
        int   pj  = __float_as_int(v2.z);
        #pragma unroll
        for (int c = 0; c < CPT; c++) {
            float dot = v0.x * xc[c][0];
            dot = fmaf(v0.y, xc[c][1], dot);
            dot = fmaf(v0.z, xc[c][2], dot);
            dot = fmaf(v0.w, xc[c][3], dot);
            dot = fmaf(v1.x, xc[c][4], dot);
            dot = fmaf(v1.y, xc[c][5], dot);
            dot = fmaf(v1.z, xc[c][6], dot);
            dot = fmaf(v1.w, xc[c][7], dot);
            float d2 = fmaf(-2.0f, dot, n2j + n2c[c]);
            if (d2 <= 1.0f) {
                float d2c = fmaxf(d2, 0.0f);
                int b = min((int)(d2c * (float)NB), NB - 1);
                atomicAdd(&s_hist[c][b], 1);
                if (pj != s_pidc[c]) {
                    float w = (1.0f - sqrtf(d2c)) * qj;
                    atomicAdd(&s_whist[c][b], w);
                }
            }
        }
    }
    __syncthreads();

    // ---- selection: boundary bin B, residual r, and wsum(bins < B) per CP ----
    if (tid < CPT) {
        int cum = 0, B = NB, r = 0; float ws = 0.0f;
        for (int b = 0; b < NB; b++) {
            int nc = cum + s_hist[tid][b];
            if (nc >= KSEL2) { B = b; r = KSEL2 - cum; break; }
            cum = nc; ws += s_whist[tid][b];
        }
        s_Bs[tid] = B; s_rs[tid] = r; s_wsum[tid] = ws;
    }
    __syncthreads();

    int Breg[CPT];
    #pragma unroll
    for (int c = 0; c < CPT; c++) Breg[c] = s_Bs[c];

    // ---- Pass B: gather boundary-bin candidates only ----
    for (int j = tid; j < N; j += RT) {
        float4 v0 = g_pack[3 * j + 0];
        float4 v1 = g_pack[3 * j + 1];
        float4 v2 = g_pack[3 * j + 2];
        float n2j = v2.x;
        #pragma unroll
        for (int c = 0; c < CPT; c++) {
            float dot = v0.x * xc[c][0];
            dot = fmaf(v0.y, xc[c][1], dot);
            dot = fmaf(v0.z, xc[c][2], dot);
            dot = fmaf(v0.w, xc[c][3], dot);
            dot = fmaf(v1.x, xc[c][4], dot);
            dot = fmaf(v1.y, xc[c][5], dot);
            dot = fmaf(v1.z, xc[c][6], dot);
            dot = fmaf(v1.w, xc[c][7], dot);
            float d2 = fmaf(-2.0f, dot, n2j + n2c[c]);
            if (d2 <= 1.0f) {
                float d2c = fmaxf(d2, 0.0f);
                int b = min((int)(d2c * (float)NB), NB - 1);
                if (b == Breg[c]) {
                    int pj = __float_as_int(v2.z);
                    float w = (pj != s_pidc[c]) ? (1.0f - sqrtf(d2c)) * v2.y : 0.0f;
                    int p = atomicAdd(&s_bcnt[c], 1);
                    if (p < BCAP) { s_bk[c][p] = __float_as_uint(d2c); s_bw[c][p] = w; }
                }
            }
        }
    }
    __syncthreads();

    // ---- boundary mini-rank + per-CP reduction ----
    #pragma unroll
    for (int c = 0; c < CPT; c++) {
        float part = 0.0f;
        int m = min(s_bcnt[c], BCAP);
        int r = s_rs[c];
        if (r > 0) {
            for (int e = tid; e < m; e += RT) {
                unsigned ke = s_bk[c][e];
                int rank = 0;
                for (int k = 0; k < m; k++) {
                    unsigned kk = s_bk[c][k];
                    rank += (kk < ke) || (kk == ke && k < e);
                }
                if (rank < r) part += s_bw[c][e];
            }
        }
        #pragma unroll
        for (int o = 16; o; o >>= 1) part += __shfl_down_sync(0xFFFFFFFFu, part, o);
        if ((tid & 31) == 0) s_red[tid >> 5] = part;
        __syncthreads();
        if (tid == 0) {
            float tot = s_wsum[c];
            #pragma unroll
            for (int w = 0; w < RT / 32; w++) tot += s_red[w];
            if (tot != 0.0f) atomicAdd(&g_rep, (double)(tot * s_qc[c]));
        }
        __syncthreads();
    }
}

__global__ void k_final(float* out, int N) {
    if (blockIdx.x == 0 && threadIdx.x == 0) {
        int mc = g_maskcnt;
        out[0] = (float)(mc > 0 ? g_att / (double)mc : 0.0);
        out[1] = (float)(g_rep / (double)N);
        out[2] = 0.0f;
        out[3] = 0.0f;
    }
}

extern "C" void kernel_launch(void* const* d_in, const int* in_sizes, int n_in,
                              void* d_out, int out_size) {
    const float* beta  = (const float*)d_in[0];
    const float* x     = (const float*)d_in[1];
    const int*   pid   = (const int*)d_in[2];
    const int*   recon = (const int*)d_in[3];
    const float* pt    = (const float*)d_in[4];
    const float* eta   = (const float*)d_in[5];
    float* out = (float*)d_out;
    int N = in_sizes[0];

    k_init<<<(NPIDMAX + 255) / 256, 256>>>();
    k_bestq<<<(N + 255) / 256, 256>>>(beta, pid, x, N);
    k_attract<<<(N + 127) / 128, 128>>>(x, pid, recon, pt, eta, N);
    int ngrp = (NPIDMAX + CPT - 1) / CPT;   // 256 blocks; ~250 active
    k_repulse<<<ngrp, RT>>>(N);
    k_final<<<1, 32>>>(out, N);
}

// round 7
// speedup vs baseline: 1.4402x; 1.4402x over previous
#include <cuda_runtime.h>
#include <math.h>

// Fixed-shape problem: N=16384, D=8, pid in [0,2000), K=128, R=1
#define NMAX    16384
#define NPIDMAX 2048
#define KSEL2   129     // top-(K+1) including self (self weight = 0)
#define CPT     4       // condensation points per repulsion block
#define RT      256     // threads per block
#define NB      256     // histogram bins over d2 in [0,1]
#define BCAP    128     // boundary-bin candidate capacity per CP

// -------- device scratch (small, allocation-free) --------
__device__ unsigned long long g_best[NPIDMAX];   // per-pid packed (beta_bits<<32 | ~idx)
__device__ float  g_q[NMAX];
__device__ float  g_n2[NMAX];
__device__ float4 g_xp[NMAX * 2];                // x packed as 2 float4 per node
__device__ int    g_cplist[NPIDMAX];
__device__ int    g_cpcount;
__device__ double g_att;
__device__ double g_rep;
__device__ int    g_maskcnt;

__global__ void k_init() {
    int i = blockIdx.x * blockDim.x + threadIdx.x;
    if (i < NPIDMAX) g_best[i] = 0ULL;
    if (i == 0) { g_cpcount = 0; g_att = 0.0; g_rep = 0.0; g_maskcnt = 0; }
}

// q = arctanh(beta)^2 + 0.01 ; |x|^2 ; pack x ; per-pid best
__global__ void k_bestq(const float* __restrict__ beta, const int* __restrict__ pid,
                        const float* __restrict__ x, int N) {
    int i = blockIdx.x * blockDim.x + threadIdx.x;
    if (i >= N) return;
    float b = beta[i];
    float t = atanhf(b);
    g_q[i] = t * t + 0.01f;
    float4 v0 = *(const float4*)(x + (size_t)i * 8);
    float4 v1 = *(const float4*)(x + (size_t)i * 8 + 4);
    float n2 = v0.x * v0.x + v0.y * v0.y + v0.z * v0.z + v0.w * v0.w
             + v1.x * v1.x + v1.y * v1.y + v1.z * v1.z + v1.w * v1.w;
    g_n2[i] = n2;
    g_xp[2 * i + 0] = v0;
    g_xp[2 * i + 1] = v1;
    int p = pid[i];
    if (p > 0 && p < NPIDMAX) {
        unsigned long long key =
            ((unsigned long long)__float_as_uint(b) << 32) |
            (unsigned long long)(0xFFFFFFFFu - (unsigned)i);
        atomicMax(&g_best[p], key);
    }
}

// compact (threads < NPIDMAX) + attraction, fused
__global__ void k_attract(const float* __restrict__ x, const int* __restrict__ pid,
                          const int* __restrict__ recon, const float* __restrict__ pt,
                          const float* __restrict__ eta, int N) {
    int i = blockIdx.x * blockDim.x + threadIdx.x;
    if (i > 0 && i < NPIDMAX) {
        unsigned long long key = g_best[i];
        if (key != 0ULL) {
            int idx = (int)(0xFFFFFFFFu - (unsigned)(key & 0xFFFFFFFFull));
            int pos = atomicAdd(&g_cpcount, 1);
            g_cplist[pos] = idx;
        }
    }
    float va = 0.0f; int m = 0;
    if (i < N) {
        int p = pid[i];
        if (p > 0 && pt[i] > 0.9f && recon[i] > 0 && fabsf(eta[i]) < 4.0f) {
            unsigned long long key = g_best[p];
            int a = (int)(0xFFFFFFFFu - (unsigned)(key & 0xFFFFFFFFull));
            const float4* xi = (const float4*)(x + (size_t)i * 8);
            const float4* xa = (const float4*)(x + (size_t)a * 8);
            float4 i0 = xi[0], i1 = xi[1], a0 = xa[0], a1 = xa[1];
            float d, d2 = 0.0f;
            d = i0.x - a0.x; d2 += d * d;
            d = i0.y - a0.y; d2 += d * d;
            d = i0.z - a0.z; d2 += d * d;
            d = i0.w - a0.w; d2 += d * d;
            d = i1.x - a1.x; d2 += d * d;
            d = i1.y - a1.y; d2 += d * d;
            d = i1.z - a1.z; d2 += d * d;
            d = i1.w - a1.w; d2 += d * d;
            va = d2 * g_q[i] * g_q[a];
            m = 1;
        }
    }
    #pragma unroll
    for (int o = 16; o; o >>= 1) {
        va += __shfl_down_sync(0xFFFFFFFFu, va, o);
        m  += __shfl_down_sync(0xFFFFFFFFu, m,  o);
    }
    if ((threadIdx.x & 31) == 0 && (m || va != 0.0f)) {
        atomicAdd(&g_att, (double)va);
        atomicAdd(&g_maskcnt, m);
    }
}

// ---- repulsion: pass A = count histogram; pass B = weights below boundary + gather ----
__global__ void __launch_bounds__(RT, 4) k_repulse(const int* __restrict__ pid, int N) {
    __shared__ int      s_hist[CPT][NB];
    __shared__ int      s_Bs[CPT];
    __shared__ int      s_rs[CPT];
    __shared__ int      s_bcnt[CPT];
    __shared__ unsigned s_bk[CPT][BCAP];
    __shared__ float    s_bw[CPT][BCAP];
    __shared__ int      s_pidc[CPT];
    __shared__ float    s_qc[CPT];
    __shared__ float    s_red[RT / 32];

    int tid   = threadIdx.x;
    int ncp   = g_cpcount;
    int cbase = blockIdx.x * CPT;
    if (cbase >= ncp) return;

    // register-resident CP coords/norms (padded slots never hit radius)
    float xc[CPT][8], n2c[CPT];
    #pragma unroll
    for (int c = 0; c < CPT; c++) {
        int slot = cbase + c;
        bool act = slot < ncp;
        int ci = act ? g_cplist[slot] : 0;
        float4 p0 = g_xp[2 * ci + 0];
        float4 p1 = g_xp[2 * ci + 1];
        xc[c][0] = p0.x; xc[c][1] = p0.y; xc[c][2] = p0.z; xc[c][3] = p0.w;
        xc[c][4] = p1.x; xc[c][5] = p1.y; xc[c][6] = p1.z; xc[c][7] = p1.w;
        n2c[c] = act ? g_n2[ci] : 1e30f;
        if (tid == 0) {
            s_pidc[c] = act ? pid[ci] : -1;
            s_qc[c]   = act ? g_q[ci] : 0.0f;
        }
    }

    for (int h = tid; h < CPT * NB; h += RT) ((int*)s_hist)[h] = 0;
    if (tid < CPT) s_bcnt[tid] = 0;
    __syncthreads();

    // ---- Pass A: count histogram of d2 (in-radius, self included) ----
    for (int j = tid; j < N; j += RT) {
        float4 v0 = g_xp[2 * j + 0];
        float4 v1 = g_xp[2 * j + 1];
        float n2j = g_n2[j];
        #pragma unroll
        for (int c = 0; c < CPT; c++) {
            float dot = v0.x * xc[c][0];
            dot = fmaf(v0.y, xc[c][1], dot);
            dot = fmaf(v0.z, xc[c][2], dot);
            dot = fmaf(v0.w, xc[c][3], dot);
            dot = fmaf(v1.x, xc[c][4], dot);
            dot = fmaf(v1.y, xc[c][5], dot);
            dot = fmaf(v1.z, xc[c][6], dot);
            dot = fmaf(v1.w, xc[c][7], dot);
            float d2 = fmaf(-2.0f, dot, n2j + n2c[c]);
            if (d2 <= 1.0f) {
                float d2c = fmaxf(d2, 0.0f);
                int b = min((int)(d2c * (float)NB), NB - 1);
                atomicAdd(&s_hist[c][b], 1);
            }
        }
    }
    __syncthreads();

    // ---- selection: boundary bin B and residual r per CP ----
    if (tid < CPT) {
        int cum = 0, B = NB, r = 0;
        for (int b = 0; b < NB; b++) {
            int nc = cum + s_hist[tid][b];
            if (nc >= KSEL2) { B = b; r = KSEL2 - cum; break; }
            cum = nc;
        }
        s_Bs[tid] = B; s_rs[tid] = r;
    }
    __syncthreads();

    int Breg[CPT];
    #pragma unroll
    for (int c = 0; c < CPT; c++) Breg[c] = s_Bs[c];

    // ---- Pass B: accumulate bins < B (lazy pid/q loads); gather boundary bin ----
    float acc[CPT];
    #pragma unroll
    for (int c = 0; c < CPT; c++) acc[c] = 0.0f;

    for (int j = tid; j < N; j += RT) {
        float4 v0 = g_xp[2 * j + 0];
        float4 v1 = g_xp[2 * j + 1];
        float n2j = g_n2[j];
        #pragma unroll
        for (int c = 0; c < CPT; c++) {
            float dot = v0.x * xc[c][0];
            dot = fmaf(v0.y, xc[c][1], dot);
            dot = fmaf(v0.z, xc[c][2], dot);
            dot = fmaf(v0.w, xc[c][3], dot);
            dot = fmaf(v1.x, xc[c][4], dot);
            dot = fmaf(v1.y, xc[c][5], dot);
            dot = fmaf(v1.z, xc[c][6], dot);
            dot = fmaf(v1.w, xc[c][7], dot);
            float d2 = fmaf(-2.0f, dot, n2j + n2c[c]);
            if (d2 <= 1.0f) {
                float d2c = fmaxf(d2, 0.0f);
                int b = min((int)(d2c * (float)NB), NB - 1);
                int B = Breg[c];
                if (b < B) {
                    if (pid[j] != s_pidc[c])
                        acc[c] += (1.0f - sqrtf(d2c)) * g_q[j];
                } else if (b == B) {
                    float w = (pid[j] != s_pidc[c]) ? (1.0f - sqrtf(d2c)) * g_q[j] : 0.0f;
                    int p = atomicAdd(&s_bcnt[c], 1);
                    if (p < BCAP) { s_bk[c][p] = __float_as_uint(d2c); s_bw[c][p] = w; }
                }
            }
        }
    }
    __syncthreads();

    // ---- boundary mini-rank + per-CP reduction ----
    #pragma unroll
    for (int c = 0; c < CPT; c++) {
        float part = acc[c];
        int m = min(s_bcnt[c], BCAP);
        int r = s_rs[c];
        if (r > 0) {
            for (int e = tid; e < m; e += RT) {
                unsigned ke = s_bk[c][e];
                int rank = 0;
                for (int k = 0; k < m; k++) {
                    unsigned kk = s_bk[c][k];
                    rank += (kk < ke) || (kk == ke && k < e);
                }
                if (rank < r) part += s_bw[c][e];
            }
        }
        #pragma unroll
        for (int o = 16; o; o >>= 1) part += __shfl_down_sync(0xFFFFFFFFu, part, o);
        if ((tid & 31) == 0) s_red[tid >> 5] = part;
        __syncthreads();
        if (tid == 0) {
            float tot = 0.0f;
            #pragma unroll
            for (int w = 0; w < RT / 32; w++) tot += s_red[w];
            if (tot != 0.0f) atomicAdd(&g_rep, (double)(tot * s_qc[c]));
        }
        __syncthreads();
    }
}

__global__ void k_final(float* out, int N) {
    if (blockIdx.x == 0 && threadIdx.x == 0) {
        int mc = g_maskcnt;
        out[0] = (float)(mc > 0 ? g_att / (double)mc : 0.0);
        out[1] = (float)(g_rep / (double)N);
        out[2] = 0.0f;
        out[3] = 0.0f;
    }
}

extern "C" void kernel_launch(void* const* d_in, const int* in_sizes, int n_in,
                              void* d_out, int out_size) {
    const float* beta  = (const float*)d_in[0];
    const float* x     = (const float*)d_in[1];
    const int*   pid   = (const int*)d_in[2];
    const int*   recon = (const int*)d_in[3];
    const float* pt    = (const float*)d_in[4];
    const float* eta   = (const float*)d_in[5];
    float* out = (float*)d_out;
    int N = in_sizes[0];

    k_init<<<(NPIDMAX + 255) / 256, 256>>>();
    k_bestq<<<(N + 255) / 256, 256>>>(beta, pid, x, N);
    k_attract<<<(N + 127) / 128, 128>>>(x, pid, recon, pt, eta, N);
    int ngrp = (NPIDMAX + CPT - 1) / CPT;   // 512 blocks; ~500 active
    k_repulse<<<ngrp, RT>>>(pid, N);
    k_final<<<1, 32>>>(out, N);
}